// round 1
// baseline (speedup 1.0000x reference)
#include <cuda_runtime.h>
#include <math.h>

#define BB 32
#define LSEQ 512
#define EIN 512
#define NMARKF 4
#define DMODEL 512
#define NHEAD 8
#define DHEAD 64
#define DFFN 2048
#define NTOK 516
#define TPAD 520
#define NHASHR 4
#define NBKT 130
#define BHD (BB*NHEAD)      /* 256 */
#define NCH 520
#define JTOT 2080           /* NHASH * TPAD */
#define MROWS (BB*TPAD)     /* 16640 */

// ---------------- scratch (device globals; no allocation allowed) -------------
__device__ __align__(16) float g_means[BB*EIN];
__device__ __align__(16) float g_stdev[BB*EIN];
__device__ __align__(16) float g_tok[MROWS*LSEQ];
__device__ __align__(16) float g_x[MROWS*DMODEL];
__device__ __align__(16) float g_qk[MROWS*DMODEL];
__device__ __align__(16) float g_vv[MROWS*DMODEL];
__device__ __align__(16) float g_t2[MROWS*DMODEL];
__device__ __align__(16) float g_ff[MROWS*DFFN];
__device__ __align__(16) float g_oh[(size_t)BHD*NHASHR*TPAD*DHEAD];
__device__ __align__(16) float g_lse[BHD*JTOT];
__device__ unsigned g_keys[BHD*JTOT];
__device__ int g_stk[BHD*JTOT];
__device__ float g_dec[BB];

// ---------------- RevIN stats ------------------------------------------------
__global__ void k_revin(const float* __restrict__ x_enc) {
    int idx = blockIdx.x * blockDim.x + threadIdx.x;
    if (idx >= BB*EIN) return;
    int b = idx >> 9, e = idx & 511;
    const float* p = x_enc + (size_t)b*LSEQ*EIN + e;
    float s = 0.f;
    for (int l = 0; l < LSEQ; l++) s += p[(size_t)l*EIN];
    float mean = s * (1.f/LSEQ);
    float q = 0.f;
    for (int l = 0; l < LSEQ; l++) { float d = p[(size_t)l*EIN] - mean; q += d*d; }
    g_means[idx] = mean;
    g_stdev[idx] = sqrtf(q*(1.f/LSEQ) + 1e-5f);
}

// ---------------- build inverted-token matrix (transpose + normalize) --------
__global__ void k_build_tok(const float* __restrict__ x_enc,
                            const float* __restrict__ x_mark) {
    __shared__ float tile[32][33];
    int b = blockIdx.z;
    int n0 = blockIdx.y * 32, l0 = blockIdx.x * 32;
    int tx = threadIdx.x, ty = threadIdx.y;
    int n = n0 + tx, l = l0 + ty;
    float val = 0.f;
    if (n < EIN) {
        float m = g_means[b*EIN + n], sd = g_stdev[b*EIN + n];
        val = (x_enc[(size_t)b*LSEQ*EIN + (size_t)l*EIN + n] - m) / sd;
    } else if (n < NTOK) {
        val = x_mark[(size_t)b*LSEQ*NMARKF + (size_t)l*NMARKF + (n - EIN)];
    }
    tile[ty][tx] = val;
    __syncthreads();
    int nw = n0 + ty, lw = l0 + tx;
    if (nw < TPAD) g_tok[((size_t)b*TPAD + nw)*LSEQ + lw] = tile[tx][ty];
}

// ---------------- generic fp32 GEMM: C = A[M,K] @ W[N,K]^T (+bias)(+relu) ----
template<bool RELU>
__global__ void k_gemm(const float* __restrict__ A, const float* __restrict__ W,
                       const float* __restrict__ bias, float* __restrict__ C,
                       int M, int N, int K) {
    __shared__ __align__(16) float As[16][64];
    __shared__ __align__(16) float Ws[16][64];
    int tid = threadIdx.x;
    int tx = tid & 15, ty = tid >> 4;
    int m0 = blockIdx.y * 64, n0 = blockIdx.x * 64;
    int lm = tid >> 2;
    int lk = (tid & 3) << 2;
    const float* Ap = A + (size_t)(m0 + lm)*K + lk;
    const float* Wq = W + (size_t)(n0 + lm)*K + lk;
    float acc[4][4] = {};
    for (int k0 = 0; k0 < K; k0 += 16) {
        float4 a4 = *(const float4*)(Ap + k0);
        float4 w4 = *(const float4*)(Wq + k0);
        As[lk+0][lm]=a4.x; As[lk+1][lm]=a4.y; As[lk+2][lm]=a4.z; As[lk+3][lm]=a4.w;
        Ws[lk+0][lm]=w4.x; Ws[lk+1][lm]=w4.y; Ws[lk+2][lm]=w4.z; Ws[lk+3][lm]=w4.w;
        __syncthreads();
#pragma unroll
        for (int k = 0; k < 16; k++) {
            float4 ar = *(const float4*)&As[k][ty<<2];
            float4 wr = *(const float4*)&Ws[k][tx<<2];
            float av[4] = {ar.x, ar.y, ar.z, ar.w};
            float wv[4] = {wr.x, wr.y, wr.z, wr.w};
#pragma unroll
            for (int i = 0; i < 4; i++)
#pragma unroll
                for (int j = 0; j < 4; j++)
                    acc[i][j] = fmaf(av[i], wv[j], acc[i][j]);
        }
        __syncthreads();
    }
#pragma unroll
    for (int i = 0; i < 4; i++) {
        size_t row = (size_t)(m0 + (ty<<2) + i)*N + n0 + (tx<<2);
#pragma unroll
        for (int j = 0; j < 4; j++) {
            float v = acc[i][j];
            if (bias) v += bias[n0 + (tx<<2) + j];
            if (RELU) v = fmaxf(v, 0.f);
            C[row + j] = v;
        }
    }
}

// ---------------- zero pad rows of residual stream ---------------------------
__global__ void k_zeropad() {
    int idx = blockIdx.x * blockDim.x + threadIdx.x;
    if (idx >= BB*4*DMODEL) return;
    int b = idx / (4*DMODEL);
    int r = idx % (4*DMODEL);
    int n = NTOK + r / DMODEL;
    int f = r % DMODEL;
    g_x[((size_t)b*TPAD + n)*DMODEL + f] = 0.f;
}

// ---------------- LSH hashing: rotated projections + argmax bucket -----------
__global__ void k_hash(const float* __restrict__ rot) {
    int gw = (blockIdx.x * blockDim.x + threadIdx.x) >> 5;
    int lane = threadIdx.x & 31;
    if (gw >= BHD*TPAD) return;
    int bh = gw / TPAD, t = gw % TPAD;
    int b = bh >> 3, hh = bh & 7;
    __shared__ float sq[4][64];
    float* qv = sq[threadIdx.x >> 5];
    const float* qp = g_qk + ((size_t)(b*TPAD + t))*DMODEL + hh*DHEAD;
    qv[lane] = qp[lane];
    qv[lane+32] = qp[lane+32];
    __syncwarp();
    for (int h = 0; h < NHASHR; h++) {
        float bv = -INFINITY; int bi = 0x7fffffff;
        for (int i = lane; i < 65; i += 32) {
            float r = 0.f;
            const float* rp = rot + h*65 + i;
#pragma unroll
            for (int f = 0; f < 64; f++) r = fmaf(qv[f], rp[f*(NHASHR*65)], r);
            if (r > bv || (r == bv && i < bi)) { bv = r; bi = i; }
            float nr = -r;
            if (nr > bv || (nr == bv && (65+i) < bi)) { bv = nr; bi = 65+i; }
        }
        for (int off = 16; off; off >>= 1) {
            float ov = __shfl_xor_sync(0xffffffffu, bv, off);
            int oi = __shfl_xor_sync(0xffffffffu, bi, off);
            if (ov > bv || (ov == bv && oi < bi)) { bv = ov; bi = oi; }
        }
        if (lane == 0) {
            unsigned key = (unsigned)((bi + h*NBKT)*TPAD + t);
            g_keys[(size_t)bh*JTOT + h*TPAD + t] = (key << 12) | (unsigned)(h*TPAD + t);
        }
    }
}

// ---------------- per-row bitonic sort (keys unique => argsort) --------------
__global__ void k_sort() {
    __shared__ unsigned sh[4096];
    int bh = blockIdx.x;
    for (int i = threadIdx.x; i < 4096; i += blockDim.x)
        sh[i] = (i < JTOT) ? g_keys[(size_t)bh*JTOT + i] : 0xffffffffu;
    __syncthreads();
    for (int k = 2; k <= 4096; k <<= 1) {
        for (int j = k >> 1; j > 0; j >>= 1) {
            for (int i = threadIdx.x; i < 4096; i += blockDim.x) {
                int ixj = i ^ j;
                if (ixj > i) {
                    unsigned a = sh[i], c = sh[ixj];
                    bool up = ((i & k) == 0);
                    if ((a > c) == up) { sh[i] = c; sh[ixj] = a; }
                }
            }
            __syncthreads();
        }
    }
    for (int p = threadIdx.x; p < JTOT; p += blockDim.x)
        g_stk[(size_t)bh*JTOT + p] = (int)(sh[p] & 0xfffu);
}

// ---------------- chunked LSH attention (warp per chunk) ---------------------
__global__ void k_attn() {
    __shared__ int   s_key[4][8];
    __shared__ int   s_pos[4][8];
    __shared__ float s_rn[4][8];
    __shared__ float s_k[4][8][64];
    __shared__ float s_v[4][8][64];
    __shared__ float s_p[4][4][8];
    __shared__ float s_l[4][4];
    int gw = (blockIdx.x * blockDim.x + threadIdx.x) >> 5;
    int lane = threadIdx.x & 31;
    int w = threadIdx.x >> 5;
    if (gw >= BHD*NCH) return;
    int bh = gw / NCH, c = gw % NCH;
    int b = bh >> 3, hh = bh & 7;
    if (lane < 8) {
        int src = (lane < 4) ? (c*4 + lane) : (((c + NCH - 1) % NCH)*4 + (lane - 4));
        int sv = g_stk[(size_t)bh*JTOT + src];
        s_key[w][lane] = sv;
        s_pos[w][lane] = sv % TPAD;
    }
    __syncwarp();
#pragma unroll
    for (int j = 0; j < 8; j++) {
        size_t base = ((size_t)(b*TPAD + s_pos[w][j]))*DMODEL + hh*DHEAD;
        s_k[w][j][lane]    = g_qk[base + lane];
        s_k[w][j][lane+32] = g_qk[base + lane + 32];
        s_v[w][j][lane]    = g_vv[base + lane];
        s_v[w][j][lane+32] = g_vv[base + lane + 32];
    }
    __syncwarp();
    if (lane < 8) {
        float s = 0.f;
#pragma unroll
        for (int f = 0; f < 64; f++) s += s_k[w][lane][f]*s_k[w][lane][f];
        s_rn[w][lane] = rsqrtf(fmaxf(s, 1e-24f));
    }
    __syncwarp();
    int qi = lane >> 3, kj = lane & 7;
    float d = 0.f;
#pragma unroll
    for (int f = 0; f < 64; f++) d = fmaf(s_k[w][qi][f], s_k[w][kj][f], d);
    d *= s_rn[w][kj] * 0.125f;   // d^-0.5 = 1/8
    if (s_pos[w][qi] == s_pos[w][kj]) d = -50000.f;
    float m = d;
    m = fmaxf(m, __shfl_xor_sync(0xffffffffu, m, 4));
    m = fmaxf(m, __shfl_xor_sync(0xffffffffu, m, 2));
    m = fmaxf(m, __shfl_xor_sync(0xffffffffu, m, 1));
    float e = expf(d - m);
    float s = e;
    s += __shfl_xor_sync(0xffffffffu, s, 4);
    s += __shfl_xor_sync(0xffffffffu, s, 2);
    s += __shfl_xor_sync(0xffffffffu, s, 1);
    s_p[w][qi][kj] = e / s;
    if (kj == 0) s_l[w][qi] = m + logf(s);
    __syncwarp();
#pragma unroll
    for (int i = 0; i < 4; i++) {
        float a0 = 0.f, a1 = 0.f;
#pragma unroll
        for (int j = 0; j < 8; j++) {
            float p = s_p[w][i][j];
            a0 = fmaf(p, s_v[w][j][lane],    a0);
            a1 = fmaf(p, s_v[w][j][lane+32], a1);
        }
        int jl = s_key[w][i];
        int hr = jl / TPAD, tp = jl % TPAD;
        float* op = g_oh + (((size_t)bh*NHASHR + hr)*TPAD + tp)*DHEAD;
        op[lane] = a0;
        op[lane+32] = a1;
        if (lane == 0) g_lse[((size_t)bh*NHASHR + hr)*TPAD + tp] = s_l[w][i];
    }
}

// ---------------- combine hash rounds (softmax over lse) ---------------------
__global__ void k_combine(float* __restrict__ attn) {
    int id = blockIdx.x;
    int bh = id / TPAD, t = id % TPAD;
    int b = bh >> 3, hh = bh & 7;
    int f = threadIdx.x;
    float l0 = g_lse[((size_t)bh*NHASHR + 0)*TPAD + t];
    float l1 = g_lse[((size_t)bh*NHASHR + 1)*TPAD + t];
    float l2 = g_lse[((size_t)bh*NHASHR + 2)*TPAD + t];
    float l3 = g_lse[((size_t)bh*NHASHR + 3)*TPAD + t];
    float m = fmaxf(fmaxf(l0, l1), fmaxf(l2, l3));
    float e0 = expf(l0-m), e1 = expf(l1-m), e2 = expf(l2-m), e3 = expf(l3-m);
    float inv = 1.f / (e0+e1+e2+e3);
    float acc =
        e0*inv*g_oh[(((size_t)bh*NHASHR + 0)*TPAD + t)*DHEAD + f] +
        e1*inv*g_oh[(((size_t)bh*NHASHR + 1)*TPAD + t)*DHEAD + f] +
        e2*inv*g_oh[(((size_t)bh*NHASHR + 2)*TPAD + t)*DHEAD + f] +
        e3*inv*g_oh[(((size_t)bh*NHASHR + 3)*TPAD + t)*DHEAD + f];
    attn[((size_t)(b*TPAD + t))*DMODEL + hh*DHEAD + f] = acc;
}

// ---------------- block reduce helper ----------------------------------------
__device__ __forceinline__ float blk_red(float v, float* sred) {
    for (int o = 16; o; o >>= 1) v += __shfl_xor_sync(0xffffffffu, v, o);
    if ((threadIdx.x & 31) == 0) sred[threadIdx.x >> 5] = v;
    __syncthreads();
    float r = sred[0] + sred[1] + sred[2] + sred[3];
    __syncthreads();
    return r;
}

// ---------------- residual add + LayerNorm (rows n < 516) --------------------
__global__ void k_addln(float* __restrict__ x, const float* __restrict__ y,
                        const float* __restrict__ gam, const float* __restrict__ bet) {
    __shared__ float sred[4];
    int r = blockIdx.x;
    int b = r / NTOK, n = r % NTOK;
    float* xr = x + ((size_t)(b*TPAD + n))*DMODEL;
    const float* yr = y + ((size_t)(b*TPAD + n))*DMODEL;
    int tid = threadIdx.x;
    float v[4]; float s = 0.f;
#pragma unroll
    for (int i = 0; i < 4; i++) { int f = tid + i*128; v[i] = xr[f] + yr[f]; s += v[i]; }
    float mean = blk_red(s, sred) * (1.f/DMODEL);
    float q = 0.f;
#pragma unroll
    for (int i = 0; i < 4; i++) { float dd = v[i]-mean; q += dd*dd; }
    float var = blk_red(q, sred) * (1.f/DMODEL);
    float rs = rsqrtf(var + 1e-5f);
#pragma unroll
    for (int i = 0; i < 4; i++) {
        int f = tid + i*128;
        xr[f] = (v[i]-mean)*rs*gam[f] + bet[f];
    }
}

// ---------------- final LN on last token + projection ------------------------
__global__ void k_final(const float* __restrict__ gF, const float* __restrict__ bF,
                        const float* __restrict__ Wp, const float* __restrict__ bp) {
    __shared__ float sred[4];
    int b = blockIdx.x, tid = threadIdx.x;
    const float* xr = g_x + ((size_t)(b*TPAD + NTOK - 1))*DMODEL;
    float v[4]; float s = 0.f;
#pragma unroll
    for (int i = 0; i < 4; i++) { int f = tid + i*128; v[i] = xr[f]; s += v[i]; }
    float mean = blk_red(s, sred) * (1.f/DMODEL);
    float q = 0.f;
#pragma unroll
    for (int i = 0; i < 4; i++) { float dd = v[i]-mean; q += dd*dd; }
    float var = blk_red(q, sred) * (1.f/DMODEL);
    float rs = rsqrtf(var + 1e-5f);
    float dot = 0.f;
#pragma unroll
    for (int i = 0; i < 4; i++) {
        int f = tid + i*128;
        float nx = (v[i]-mean)*rs*gF[f] + bF[f];
        dot = fmaf(nx, Wp[f], dot);
    }
    float tot = blk_red(dot, sred);
    if (tid == 0) g_dec[b] = tot + bp[0];
}

// ---------------- output: dec[j]*stdev[i,e] + means[i,e] ---------------------
__global__ void k_out(float* __restrict__ out) {
    int idx = blockIdx.x * blockDim.x + threadIdx.x;
    if (idx >= BB*BB*EIN) return;
    int e = idx & 511;
    int j = (idx >> 9) & 31;
    int i = idx >> 14;
    out[idx] = g_dec[j]*g_stdev[i*EIN + e] + g_means[i*EIN + e];
}

// ---------------- host-side orchestration ------------------------------------
static void run_gemm(const float* A, const float* W, const float* bias, float* C,
                     int M, int N, int K, bool relu) {
    dim3 grid(N/64, M/64);
    if (relu) k_gemm<true><<<grid, 256>>>(A, W, bias, C, M, N, K);
    else      k_gemm<false><<<grid, 256>>>(A, W, bias, C, M, N, K);
}

extern "C" void kernel_launch(void* const* d_in, const int* in_sizes, int n_in,
                              void* d_out, int out_size) {
    const float* x_enc  = (const float*)d_in[0];
    const float* x_mark = (const float*)d_in[1];
    const float* W_emb  = (const float*)d_in[2];
    const float* b_emb  = (const float*)d_in[3];
    const float* Wqk    = (const float*)d_in[4];
    const float* Wv     = (const float*)d_in[5];
    const float* Wo     = (const float*)d_in[6];
    const float* bo     = (const float*)d_in[7];
    const float* Wc1    = (const float*)d_in[8];
    const float* bc1    = (const float*)d_in[9];
    const float* Wc2    = (const float*)d_in[10];
    const float* bc2    = (const float*)d_in[11];
    const float* g1     = (const float*)d_in[12];
    const float* b1     = (const float*)d_in[13];
    const float* g2     = (const float*)d_in[14];
    const float* b2     = (const float*)d_in[15];
    const float* gF     = (const float*)d_in[16];
    const float* bF     = (const float*)d_in[17];
    const float* Wp     = (const float*)d_in[18];
    const float* bp     = (const float*)d_in[19];
    const float* rot    = (const float*)d_in[20];

    float *p_tok, *p_x, *p_qk, *p_v, *p_t2, *p_ff;
    cudaGetSymbolAddress((void**)&p_tok, g_tok);
    cudaGetSymbolAddress((void**)&p_x,   g_x);
    cudaGetSymbolAddress((void**)&p_qk,  g_qk);
    cudaGetSymbolAddress((void**)&p_v,   g_vv);
    cudaGetSymbolAddress((void**)&p_t2,  g_t2);
    cudaGetSymbolAddress((void**)&p_ff,  g_ff);

    // 1. RevIN stats
    k_revin<<<(BB*EIN + 255)/256, 256>>>(x_enc);
    // 2. token matrix (normalize + transpose + marks + zero pad)
    k_build_tok<<<dim3(16, 17, BB), dim3(32, 32)>>>(x_enc, x_mark);
    // 3. embedding
    run_gemm(p_tok, W_emb, b_emb, p_x, MROWS, DMODEL, LSEQ, false);
    // 4. zero pad rows of x (b_emb leaked into them)
    k_zeropad<<<(BB*4*DMODEL + 255)/256, 256>>>();

    for (int l = 0; l < 2; l++) {
        const float* Wqk_l = Wqk + (size_t)l*DMODEL*DMODEL;
        const float* Wv_l  = Wv  + (size_t)l*DMODEL*DMODEL;
        const float* Wo_l  = Wo  + (size_t)l*DMODEL*DMODEL;
        const float* bo_l  = bo  + (size_t)l*DMODEL;
        const float* Wc1_l = Wc1 + (size_t)l*DFFN*DMODEL;
        const float* bc1_l = bc1 + (size_t)l*DFFN;
        const float* Wc2_l = Wc2 + (size_t)l*DMODEL*DFFN;
        const float* bc2_l = bc2 + (size_t)l*DMODEL;
        const float* rot_l = rot + (size_t)l*DHEAD*NHASHR*65;

        run_gemm(p_x, Wqk_l, nullptr, p_qk, MROWS, DMODEL, DMODEL, false);
        run_gemm(p_x, Wv_l,  nullptr, p_v,  MROWS, DMODEL, DMODEL, false);
        k_hash<<<(BHD*TPAD*32)/128, 128>>>(rot_l);
        k_sort<<<BHD, 512>>>();
        k_attn<<<(BHD*NCH*32)/128, 128>>>();
        k_combine<<<BHD*TPAD, 64>>>(p_ff);
        run_gemm(p_ff, Wo_l, bo_l, p_t2, MROWS, DMODEL, DMODEL, false);
        k_addln<<<BB*NTOK, 128>>>(p_x, p_t2, g1 + l*DMODEL, b1 + l*DMODEL);
        run_gemm(p_x, Wc1_l, bc1_l, p_ff, MROWS, DFFN, DMODEL, true);
        run_gemm(p_ff, Wc2_l, bc2_l, p_t2, MROWS, DMODEL, DFFN, false);
        k_addln<<<BB*NTOK, 128>>>(p_x, p_t2, g2 + l*DMODEL, b2 + l*DMODEL);
    }

    k_final<<<BB, 128>>>(gF, bF, Wp, bp);
    k_out<<<(BB*BB*EIN + 255)/256, 256>>>((float*)d_out);
}

// round 4
// speedup vs baseline: 1.2943x; 1.2943x over previous
#include <cuda_runtime.h>
#include <math.h>

#define BB 32
#define LSEQ 512
#define EIN 512
#define NMARKF 4
#define DMODEL 512
#define NHEAD 8
#define DHEAD 64
#define DFFN 2048
#define NTOK 516
#define TPAD 520
#define NHASHR 4
#define NBKT 130
#define BHD (BB*NHEAD)      /* 256 */
#define NCH 520
#define JTOT 2080           /* NHASH * TPAD */
#define MROWS (BB*TPAD)     /* 16640 */

// ---------------- scratch (device globals; no allocation allowed) -------------
__device__ __align__(16) float g_means[BB*EIN];
__device__ __align__(16) float g_stdev[BB*EIN];
__device__ __align__(16) float g_tok[MROWS*LSEQ];
__device__ __align__(16) float g_x[MROWS*DMODEL];
__device__ __align__(16) float g_qk[MROWS*DMODEL];
__device__ __align__(16) float g_vv[MROWS*DMODEL];
__device__ __align__(16) float g_t2[MROWS*DMODEL];
__device__ __align__(16) float g_ff[MROWS*DFFN];
__device__ __align__(16) float g_oh[(size_t)BHD*NHASHR*TPAD*DHEAD];
__device__ __align__(16) float g_lse[BHD*JTOT];
__device__ unsigned g_keys[BHD*JTOT];
__device__ int g_stk[BHD*JTOT];
__device__ float g_dec[BB];

// ---------------- RevIN stats ------------------------------------------------
__global__ void k_revin(const float* __restrict__ x_enc) {
    int idx = blockIdx.x * blockDim.x + threadIdx.x;
    if (idx >= BB*EIN) return;
    int b = idx >> 9, e = idx & 511;
    const float* p = x_enc + (size_t)b*LSEQ*EIN + e;
    float s = 0.f;
    for (int l = 0; l < LSEQ; l++) s += p[(size_t)l*EIN];
    float mean = s * (1.f/LSEQ);
    float q = 0.f;
    for (int l = 0; l < LSEQ; l++) { float d = p[(size_t)l*EIN] - mean; q += d*d; }
    g_means[idx] = mean;
    g_stdev[idx] = sqrtf(q*(1.f/LSEQ) + 1e-5f);
}

// ---------------- build inverted-token matrix (transpose + normalize) --------
__global__ void k_build_tok(const float* __restrict__ x_enc,
                            const float* __restrict__ x_mark) {
    __shared__ float tile[32][33];
    int b = blockIdx.z;
    int n0 = blockIdx.y * 32, l0 = blockIdx.x * 32;
    int tx = threadIdx.x, ty = threadIdx.y;
    int n = n0 + tx, l = l0 + ty;
    float val = 0.f;
    if (n < EIN) {
        float m = g_means[b*EIN + n], sd = g_stdev[b*EIN + n];
        val = (x_enc[(size_t)b*LSEQ*EIN + (size_t)l*EIN + n] - m) / sd;
    } else if (n < NTOK) {
        val = x_mark[(size_t)b*LSEQ*NMARKF + (size_t)l*NMARKF + (n - EIN)];
    }
    tile[ty][tx] = val;
    __syncthreads();
    int nw = n0 + ty, lw = l0 + tx;
    if (nw < TPAD) g_tok[((size_t)b*TPAD + nw)*LSEQ + lw] = tile[tx][ty];
}

// ---------------- fp32 GEMM via packed fma.rn.f32x2 (FFMA2) ------------------
// C = A[M,K] @ W[N,K]^T (+bias)(+relu)(+zeropad of rows with row%TPAD>=NTOK)
// 128x128 tile, 256 threads, 8x8 microtile, double-buffered smem,
// strictly sequential k-accumulation per output element (bit-identical to
// scalar fmaf chain -> LSH buckets unchanged).
template<bool RELU, bool ZPAD>
__global__ __launch_bounds__(256, 2)
void k_gemm2(const float* __restrict__ A, const float* __restrict__ W,
             const float* __restrict__ bias, float* __restrict__ C,
             int M, int N, int K) {
    __shared__ __align__(16) float As[2][8][132];
    __shared__ __align__(16) float Ws[2][8][132];
    int tid = threadIdx.x;
    int m0 = blockIdx.y * 128, n0 = blockIdx.x * 128;
    int r = tid >> 1, kq = (tid & 1) << 2;
    const float* Ap = A + (size_t)(m0 + r)*K + kq;
    const float* Wq = W + (size_t)(n0 + r)*K + kq;
    int w = tid >> 5, lane = tid & 31;
    int wm = w >> 2, wn = w & 3;
    int lm = lane >> 2, ln = lane & 3;
    int fm = wm*64 + lm*8;
    int fn = wn*32 + ln*8;

    unsigned long long acc[8][4];
#pragma unroll
    for (int i = 0; i < 8; i++)
#pragma unroll
        for (int j = 0; j < 4; j++) acc[i][j] = 0ull;

    float4 a4 = *(const float4*)(Ap);
    float4 w4 = *(const float4*)(Wq);
    As[0][kq+0][r]=a4.x; As[0][kq+1][r]=a4.y; As[0][kq+2][r]=a4.z; As[0][kq+3][r]=a4.w;
    Ws[0][kq+0][r]=w4.x; Ws[0][kq+1][r]=w4.y; Ws[0][kq+2][r]=w4.z; Ws[0][kq+3][r]=w4.w;
    __syncthreads();

    int nstage = K >> 3;
    int buf = 0;
    for (int s = 0; s < nstage; s++) {
        if (s + 1 < nstage) {
            a4 = *(const float4*)(Ap + (s+1)*8);
            w4 = *(const float4*)(Wq + (s+1)*8);
        }
#pragma unroll
        for (int k = 0; k < 8; k++) {
            float4 af0 = *(const float4*)&As[buf][k][fm];
            float4 af1 = *(const float4*)&As[buf][k][fm+4];
            const unsigned long long* pw = (const unsigned long long*)&Ws[buf][k][fn];
            unsigned long long bb0 = pw[0], bb1 = pw[1], bb2 = pw[2], bb3 = pw[3];
            float av[8] = {af0.x, af0.y, af0.z, af0.w, af1.x, af1.y, af1.z, af1.w};
#pragma unroll
            for (int i = 0; i < 8; i++) {
                unsigned long long aa;
                asm("mov.b64 %0, {%1, %1};" : "=l"(aa) : "f"(av[i]));
                asm("fma.rn.f32x2 %0, %1, %2, %0;" : "+l"(acc[i][0]) : "l"(aa), "l"(bb0));
                asm("fma.rn.f32x2 %0, %1, %2, %0;" : "+l"(acc[i][1]) : "l"(aa), "l"(bb1));
                asm("fma.rn.f32x2 %0, %1, %2, %0;" : "+l"(acc[i][2]) : "l"(aa), "l"(bb2));
                asm("fma.rn.f32x2 %0, %1, %2, %0;" : "+l"(acc[i][3]) : "l"(aa), "l"(bb3));
            }
        }
        if (s + 1 < nstage) {
            int nb = buf ^ 1;
            As[nb][kq+0][r]=a4.x; As[nb][kq+1][r]=a4.y; As[nb][kq+2][r]=a4.z; As[nb][kq+3][r]=a4.w;
            Ws[nb][kq+0][r]=w4.x; Ws[nb][kq+1][r]=w4.y; Ws[nb][kq+2][r]=w4.z; Ws[nb][kq+3][r]=w4.w;
            __syncthreads();
            buf = nb;
        }
    }

#pragma unroll
    for (int i = 0; i < 8; i++) {
        int m = m0 + fm + i;
        int n = n0 + fn;
        float o[8];
#pragma unroll
        for (int j = 0; j < 4; j++) {
            float lo, hi;
            asm("mov.b64 {%0, %1}, %2;" : "=f"(lo), "=f"(hi) : "l"(acc[i][j]));
            o[2*j] = lo; o[2*j+1] = hi;
        }
        if (bias) {
#pragma unroll
            for (int j = 0; j < 8; j++) o[j] += bias[n + j];
        }
        if (RELU) {
#pragma unroll
            for (int j = 0; j < 8; j++) o[j] = fmaxf(o[j], 0.f);
        }
        if (ZPAD && (m % TPAD) >= NTOK) {
#pragma unroll
            for (int j = 0; j < 8; j++) o[j] = 0.f;
        }
        float4* cp = (float4*)(C + (size_t)m*N + n);
        cp[0] = make_float4(o[0], o[1], o[2], o[3]);
        cp[1] = make_float4(o[4], o[5], o[6], o[7]);
    }
}

// ---------------- LSH hashing: rotated projections + argmax bucket -----------
__global__ void k_hash(const float* __restrict__ rot) {
    int gw = (blockIdx.x * blockDim.x + threadIdx.x) >> 5;
    int lane = threadIdx.x & 31;
    if (gw >= BHD*TPAD) return;
    int bh = gw / TPAD, t = gw % TPAD;
    int b = bh >> 3, hh = bh & 7;
    __shared__ float sq[4][64];
    float* qv = sq[threadIdx.x >> 5];
    const float* qp = g_qk + ((size_t)(b*TPAD + t))*DMODEL + hh*DHEAD;
    qv[lane] = qp[lane];
    qv[lane+32] = qp[lane+32];
    __syncwarp();
    for (int h = 0; h < NHASHR; h++) {
        float bv = -INFINITY; int bi = 0x7fffffff;
        for (int i = lane; i < 65; i += 32) {
            float r = 0.f;
            const float* rp = rot + h*65 + i;
#pragma unroll
            for (int f = 0; f < 64; f++) r = fmaf(qv[f], rp[f*(NHASHR*65)], r);
            if (r > bv || (r == bv && i < bi)) { bv = r; bi = i; }
            float nr = -r;
            if (nr > bv || (nr == bv && (65+i) < bi)) { bv = nr; bi = 65+i; }
        }
        for (int off = 16; off; off >>= 1) {
            float ov = __shfl_xor_sync(0xffffffffu, bv, off);
            int oi = __shfl_xor_sync(0xffffffffu, bi, off);
            if (ov > bv || (ov == bv && oi < bi)) { bv = ov; bi = oi; }
        }
        if (lane == 0) {
            unsigned key = (unsigned)((bi + h*NBKT)*TPAD + t);
            g_keys[(size_t)bh*JTOT + h*TPAD + t] = (key << 12) | (unsigned)(h*TPAD + t);
        }
    }
}

// ---------------- per-row bitonic sort (keys unique => argsort) --------------
__global__ void k_sort() {
    __shared__ unsigned sh[4096];
    int bh = blockIdx.x;
    for (int i = threadIdx.x; i < 4096; i += blockDim.x)
        sh[i] = (i < JTOT) ? g_keys[(size_t)bh*JTOT + i] : 0xffffffffu;
    __syncthreads();
    for (int k = 2; k <= 4096; k <<= 1) {
        for (int j = k >> 1; j > 0; j >>= 1) {
            for (int i = threadIdx.x; i < 4096; i += blockDim.x) {
                int ixj = i ^ j;
                if (ixj > i) {
                    unsigned a = sh[i], c = sh[ixj];
                    bool up = ((i & k) == 0);
                    if ((a > c) == up) { sh[i] = c; sh[ixj] = a; }
                }
            }
            __syncthreads();
        }
    }
    for (int p = threadIdx.x; p < JTOT; p += blockDim.x)
        g_stk[(size_t)bh*JTOT + p] = (int)(sh[p] & 0xfffu);
}

// ---------------- chunked LSH attention (warp per chunk) ---------------------
__global__ void k_attn() {
    __shared__ int   s_key[4][8];
    __shared__ int   s_pos[4][8];
    __shared__ float s_rn[4][8];
    __shared__ float s_k[4][8][64];
    __shared__ float s_v[4][8][64];
    __shared__ float s_p[4][4][8];
    __shared__ float s_l[4][4];
    int gw = (blockIdx.x * blockDim.x + threadIdx.x) >> 5;
    int lane = threadIdx.x & 31;
    int w = threadIdx.x >> 5;
    if (gw >= BHD*NCH) return;
    int bh = gw / NCH, c = gw % NCH;
    int b = bh >> 3, hh = bh & 7;
    if (lane < 8) {
        int src = (lane < 4) ? (c*4 + lane) : (((c + NCH - 1) % NCH)*4 + (lane - 4));
        int sv = g_stk[(size_t)bh*JTOT + src];
        s_key[w][lane] = sv;
        s_pos[w][lane] = sv % TPAD;
    }
    __syncwarp();
#pragma unroll
    for (int j = 0; j < 8; j++) {
        size_t base = ((size_t)(b*TPAD + s_pos[w][j]))*DMODEL + hh*DHEAD;
        s_k[w][j][lane]    = g_qk[base + lane];
        s_k[w][j][lane+32] = g_qk[base + lane + 32];
        s_v[w][j][lane]    = g_vv[base + lane];
        s_v[w][j][lane+32] = g_vv[base + lane + 32];
    }
    __syncwarp();
    if (lane < 8) {
        float s = 0.f;
#pragma unroll
        for (int f = 0; f < 64; f++) s += s_k[w][lane][f]*s_k[w][lane][f];
        s_rn[w][lane] = rsqrtf(fmaxf(s, 1e-24f));
    }
    __syncwarp();
    int qi = lane >> 3, kj = lane & 7;
    float d = 0.f;
#pragma unroll
    for (int f = 0; f < 64; f++) d = fmaf(s_k[w][qi][f], s_k[w][kj][f], d);
    d *= s_rn[w][kj] * 0.125f;
    if (s_pos[w][qi] == s_pos[w][kj]) d = -50000.f;
    float m = d;
    m = fmaxf(m, __shfl_xor_sync(0xffffffffu, m, 4));
    m = fmaxf(m, __shfl_xor_sync(0xffffffffu, m, 2));
    m = fmaxf(m, __shfl_xor_sync(0xffffffffu, m, 1));
    float e = expf(d - m);
    float s = e;
    s += __shfl_xor_sync(0xffffffffu, s, 4);
    s += __shfl_xor_sync(0xffffffffu, s, 2);
    s += __shfl_xor_sync(0xffffffffu, s, 1);
    s_p[w][qi][kj] = e / s;
    if (kj == 0) s_l[w][qi] = m + logf(s);
    __syncwarp();
#pragma unroll
    for (int i = 0; i < 4; i++) {
        float a0 = 0.f, a1 = 0.f;
#pragma unroll
        for (int j = 0; j < 8; j++) {
            float p = s_p[w][i][j];
            a0 = fmaf(p, s_v[w][j][lane],    a0);
            a1 = fmaf(p, s_v[w][j][lane+32], a1);
        }
        int jl = s_key[w][i];
        int hr = jl / TPAD, tp = jl % TPAD;
        float* op = g_oh + (((size_t)bh*NHASHR + hr)*TPAD + tp)*DHEAD;
        op[lane] = a0;
        op[lane+32] = a1;
        if (lane == 0) g_lse[((size_t)bh*NHASHR + hr)*TPAD + tp] = s_l[w][i];
    }
}

// ---------------- combine hash rounds (softmax over lse) ---------------------
__global__ void k_combine(float* __restrict__ attn) {
    int id = blockIdx.x;
    int bh = id / TPAD, t = id % TPAD;
    int b = bh >> 3, hh = bh & 7;
    int f = threadIdx.x;
    float l0 = g_lse[((size_t)bh*NHASHR + 0)*TPAD + t];
    float l1 = g_lse[((size_t)bh*NHASHR + 1)*TPAD + t];
    float l2 = g_lse[((size_t)bh*NHASHR + 2)*TPAD + t];
    float l3 = g_lse[((size_t)bh*NHASHR + 3)*TPAD + t];
    float m = fmaxf(fmaxf(l0, l1), fmaxf(l2, l3));
    float e0 = expf(l0-m), e1 = expf(l1-m), e2 = expf(l2-m), e3 = expf(l3-m);
    float inv = 1.f / (e0+e1+e2+e3);
    float acc =
        e0*inv*g_oh[(((size_t)bh*NHASHR + 0)*TPAD + t)*DHEAD + f] +
        e1*inv*g_oh[(((size_t)bh*NHASHR + 1)*TPAD + t)*DHEAD + f] +
        e2*inv*g_oh[(((size_t)bh*NHASHR + 2)*TPAD + t)*DHEAD + f] +
        e3*inv*g_oh[(((size_t)bh*NHASHR + 3)*TPAD + t)*DHEAD + f];
    attn[((size_t)(b*TPAD + t))*DMODEL + hh*DHEAD + f] = acc;
}

// ---------------- block reduce helper ----------------------------------------
__device__ __forceinline__ float blk_red(float v, float* sred) {
    for (int o = 16; o; o >>= 1) v += __shfl_xor_sync(0xffffffffu, v, o);
    if ((threadIdx.x & 31) == 0) sred[threadIdx.x >> 5] = v;
    __syncthreads();
    float r = sred[0] + sred[1] + sred[2] + sred[3];
    __syncthreads();
    return r;
}

// ---------------- residual add + LayerNorm (rows n < 516) --------------------
__global__ void k_addln(float* __restrict__ x, const float* __restrict__ y,
                        const float* __restrict__ gam, const float* __restrict__ bet) {
    __shared__ float sred[4];
    int r = blockIdx.x;
    int b = r / NTOK, n = r % NTOK;
    float* xr = x + ((size_t)(b*TPAD + n))*DMODEL;
    const float* yr = y + ((size_t)(b*TPAD + n))*DMODEL;
    int tid = threadIdx.x;
    float v[4]; float s = 0.f;
#pragma unroll
    for (int i = 0; i < 4; i++) { int f = tid + i*128; v[i] = xr[f] + yr[f]; s += v[i]; }
    float mean = blk_red(s, sred) * (1.f/DMODEL);
    float q = 0.f;
#pragma unroll
    for (int i = 0; i < 4; i++) { float dd = v[i]-mean; q += dd*dd; }
    float var = blk_red(q, sred) * (1.f/DMODEL);
    float rs = rsqrtf(var + 1e-5f);
#pragma unroll
    for (int i = 0; i < 4; i++) {
        int f = tid + i*128;
        xr[f] = (v[i]-mean)*rs*gam[f] + bet[f];
    }
}

// ---------------- final LN on last token + projection ------------------------
__global__ void k_final(const float* __restrict__ gF, const float* __restrict__ bF,
                        const float* __restrict__ Wp, const float* __restrict__ bp) {
    __shared__ float sred[4];
    int b = blockIdx.x, tid = threadIdx.x;
    const float* xr = g_x + ((size_t)(b*TPAD + NTOK - 1))*DMODEL;
    float v[4]; float s = 0.f;
#pragma unroll
    for (int i = 0; i < 4; i++) { int f = tid + i*128; v[i] = xr[f]; s += v[i]; }
    float mean = blk_red(s, sred) * (1.f/DMODEL);
    float q = 0.f;
#pragma unroll
    for (int i = 0; i < 4; i++) { float dd = v[i]-mean; q += dd*dd; }
    float var = blk_red(q, sred) * (1.f/DMODEL);
    float rs = rsqrtf(var + 1e-5f);
    float dot = 0.f;
#pragma unroll
    for (int i = 0; i < 4; i++) {
        int f = tid + i*128;
        float nx = (v[i]-mean)*rs*gF[f] + bF[f];
        dot = fmaf(nx, Wp[f], dot);
    }
    float tot = blk_red(dot, sred);
    if (tid == 0) g_dec[b] = tot + bp[0];
}

// ---------------- output: dec[j]*stdev[i,e] + means[i,e] ---------------------
__global__ void k_out(float* __restrict__ out) {
    int idx = blockIdx.x * blockDim.x + threadIdx.x;
    if (idx >= BB*BB*EIN) return;
    int e = idx & 511;
    int j = (idx >> 9) & 31;
    int i = idx >> 14;
    out[idx] = g_dec[j]*g_stdev[i*EIN + e] + g_means[i*EIN + e];
}

// ---------------- host-side orchestration ------------------------------------
static void run_gemm(const float* A, const float* W, const float* bias, float* C,
                     int M, int N, int K, bool relu, bool zpad) {
    dim3 grid(N/128, M/128);
    if (zpad)       k_gemm2<false, true><<<grid, 256>>>(A, W, bias, C, M, N, K);
    else if (relu)  k_gemm2<true, false><<<grid, 256>>>(A, W, bias, C, M, N, K);
    else            k_gemm2<false,false><<<grid, 256>>>(A, W, bias, C, M, N, K);
}

extern "C" void kernel_launch(void* const* d_in, const int* in_sizes, int n_in,
                              void* d_out, int out_size) {
    const float* x_enc  = (const float*)d_in[0];
    const float* x_mark = (const float*)d_in[1];
    const float* W_emb  = (const float*)d_in[2];
    const float* b_emb  = (const float*)d_in[3];
    const float* Wqk    = (const float*)d_in[4];
    const float* Wv     = (const float*)d_in[5];
    const float* Wo     = (const float*)d_in[6];
    const float* bo     = (const float*)d_in[7];
    const float* Wc1    = (const float*)d_in[8];
    const float* bc1    = (const float*)d_in[9];
    const float* Wc2    = (const float*)d_in[10];
    const float* bc2    = (const float*)d_in[11];
    const float* g1     = (const float*)d_in[12];
    const float* b1     = (const float*)d_in[13];
    const float* g2     = (const float*)d_in[14];
    const float* b2     = (const float*)d_in[15];
    const float* gF     = (const float*)d_in[16];
    const float* bF     = (const float*)d_in[17];
    const float* Wp     = (const float*)d_in[18];
    const float* bp     = (const float*)d_in[19];
    const float* rot    = (const float*)d_in[20];

    float *p_tok, *p_x, *p_qk, *p_v, *p_t2, *p_ff;
    cudaGetSymbolAddress((void**)&p_tok, g_tok);
    cudaGetSymbolAddress((void**)&p_x,   g_x);
    cudaGetSymbolAddress((void**)&p_qk,  g_qk);
    cudaGetSymbolAddress((void**)&p_v,   g_vv);
    cudaGetSymbolAddress((void**)&p_t2,  g_t2);
    cudaGetSymbolAddress((void**)&p_ff,  g_ff);

    // 1. RevIN stats
    k_revin<<<(BB*EIN + 255)/256, 256>>>(x_enc);
    // 2. token matrix (normalize + transpose + marks)
    k_build_tok<<<dim3(16, 17, BB), dim3(32, 32)>>>(x_enc, x_mark);
    // 3. embedding (+ zero pad rows in epilogue)
    run_gemm(p_tok, W_emb, b_emb, p_x, MROWS, DMODEL, LSEQ, false, true);

    for (int l = 0; l < 2; l++) {
        const float* Wqk_l = Wqk + (size_t)l*DMODEL*DMODEL;
        const float* Wv_l  = Wv  + (size_t)l*DMODEL*DMODEL;
        const float* Wo_l  = Wo  + (size_t)l*DMODEL*DMODEL;
        const float* bo_l  = bo  + (size_t)l*DMODEL;
        const float* Wc1_l = Wc1 + (size_t)l*DFFN*DMODEL;
        const float* bc1_l = bc1 + (size_t)l*DFFN;
        const float* Wc2_l = Wc2 + (size_t)l*DMODEL*DFFN;
        const float* bc2_l = bc2 + (size_t)l*DMODEL;
        const float* rot_l = rot + (size_t)l*DHEAD*NHASHR*65;

        run_gemm(p_x, Wqk_l, nullptr, p_qk, MROWS, DMODEL, DMODEL, false, false);
        run_gemm(p_x, Wv_l,  nullptr, p_v,  MROWS, DMODEL, DMODEL, false, false);
        k_hash<<<(BHD*TPAD*32)/128, 128>>>(rot_l);
        k_sort<<<BHD, 512>>>();
        k_attn<<<(BHD*NCH*32)/128, 128>>>();
        k_combine<<<BHD*TPAD, 64>>>(p_ff);
        run_gemm(p_ff, Wo_l, bo_l, p_t2, MROWS, DMODEL, DMODEL, false, false);
        k_addln<<<BB*NTOK, 128>>>(p_x, p_t2, g1 + l*DMODEL, b1 + l*DMODEL);
        run_gemm(p_x, Wc1_l, bc1_l, p_ff, MROWS, DFFN, DMODEL, true, false);
        run_gemm(p_ff, Wc2_l, bc2_l, p_t2, MROWS, DMODEL, DFFN, false, false);
        k_addln<<<BB*NTOK, 128>>>(p_x, p_t2, g2 + l*DMODEL, b2 + l*DMODEL);
    }

    k_final<<<BB, 128>>>(gF, bF, Wp, bp);
    k_out<<<(BB*BB*EIN + 255)/256, 256>>>((float*)d_out);
}